// round 1
// baseline (speedup 1.0000x reference)
#include <cuda_runtime.h>
#include <cstdint>

#define HH 48
#define CCH 32
#define PP 56
#define PAD 4
#define X2P_CH (PP*PP*PP)          /* 175616 */
#define X1_CH  (HH*HH*HH)          /* 110592 */

#define TH 8
#define TW 8
#define NSEG 6
#define NTHREADS 384
#define S2 60                      /* x2 smem row stride (floats), conflict-free */
#define S1 52                     /* x1 smem row stride (floats), conflict-free */
#define X2BUF (64*S2)              /* 3840 floats per buffer */
#define X1BUF (64*S1)              /* 3328 floats per buffer */
#define SMEM_FLOATS (2*X2BUF + 2*X1BUF)   /* 14336 floats = 57344 B */

// Zero-padded x2: [C][56][56][56]
__device__ float g_x2p[CCH * X2P_CH];

__global__ void pad_kernel(const float* __restrict__ x2) {
    int idx = blockIdx.x * blockDim.x + threadIdx.x;   // exactly 32*175616 threads
    int c   = idx / X2P_CH;
    int rem = idx % X2P_CH;
    int hp  = rem / (PP*PP);
    int wp  = (rem / PP) % PP;
    int dp  = rem % PP;
    int h = hp - PAD, w = wp - PAD, d = dp - PAD;
    float v = 0.f;
    if ((unsigned)h < HH && (unsigned)w < HH && (unsigned)d < HH)
        v = x2[((c*HH + h)*HH + w)*HH + d];
    g_x2p[idx] = v;
}

__device__ __forceinline__ void cp_async16(uint32_t s, const void* g) {
    asm volatile("cp.async.cg.shared.global [%0], [%1], 16;" :: "r"(s), "l"(g));
}
__device__ __forceinline__ void cp_commit() { asm volatile("cp.async.commit_group;"); }
__device__ __forceinline__ void cp_wait1()  { asm volatile("cp.async.wait_group 1;"); }

// Grid: (6 w-tiles, 6 h-tiles, 81 (i,j) pairs). Block: 384 threads.
// Thread (lh, lw, seg) owns output voxels (h0+lh, w0+lw, seg*8 .. seg*8+7)
// for all 9 k-offsets of the CTA's fixed (i,j).
__global__ void __launch_bounds__(NTHREADS, 1)
corr_kernel(const float* __restrict__ x1, float* __restrict__ out)
{
    extern __shared__ float smem[];
    const int tid = threadIdx.x;
    const int lw  = tid & 7;            // 0..7 (fastest → conflict-free LDS phases)
    const int seg = (tid >> 3) % NSEG;  // 0..5
    const int lh  = tid / 48;           // 0..7
    const int w0  = blockIdx.x * TW;
    const int h0  = blockIdx.y * TH;
    const int ij  = blockIdx.z;
    const int oi  = ij / 9;
    const int oj  = ij % 9;

    uint32_t smem_u32 = (uint32_t)__cvta_generic_to_shared(smem);

    // ---- Precompute cooperative-load slots (x2 slab: 896 float4, x1 slab: 768 float4) ----
    const char* gsrc[5];
    int         gstep[5];
    uint32_t    sdst[5];
    int         sstep[5];
    bool        valid[5];
    #pragma unroll
    for (int s = 0; s < 5; s++) {
        int t = tid + s * NTHREADS;
        valid[s] = (t < 1664);
        if (t < 896) {                       // x2p slab: rows = (lh,lw) 8x8, 14 float4/row
            int row = t / 14, col = t % 14;
            int hp = h0 + oi + (row >> 3);
            int wp = w0 + oj + (row & 7);
            gsrc[s]  = (const char*)(g_x2p + ((size_t)hp*PP + wp)*PP + col*4);
            gstep[s] = X2P_CH * 4;
            sdst[s]  = smem_u32 + (uint32_t)(row*S2 + col*4)*4;
            sstep[s] = X2BUF * 4;
        } else {                             // x1 slab: rows 8x8, 12 float4/row
            int u = (t - 896) & 1023;        // keep in range even if invalid
            int row = u / 12, col = u % 12;
            if (row > 63) row = 63;
            int hh = h0 + (row >> 3);
            int ww = w0 + (row & 7);
            gsrc[s]  = (const char*)(x1 + ((size_t)hh*HH + ww)*HH + col*4);
            gstep[s] = X1_CH * 4;
            sdst[s]  = smem_u32 + (uint32_t)(2*X2BUF + row*S1 + col*4)*4;
            sstep[s] = X1BUF * 4;
        }
    }

    float acc[9][8];
    #pragma unroll
    for (int k = 0; k < 9; k++)
        #pragma unroll
        for (int r = 0; r < 8; r++) acc[k][r] = 0.f;

    // Prologue: load channel 0 into buffer 0
    #pragma unroll
    for (int s = 0; s < 5; s++)
        if (valid[s]) cp_async16(sdst[s], gsrc[s]);
    cp_commit();

    const float* xbase = smem + 2*X2BUF + (lh*8 + lw)*S1 + seg*8;
    const float* wbase = smem +            (lh*8 + lw)*S2 + seg*8;

    #pragma unroll 1
    for (int c = 0; c < CCH; c++) {
        const int b = c & 1;
        if (c + 1 < CCH) {
            const int nb = 1 - b;
            #pragma unroll
            for (int s = 0; s < 5; s++)
                if (valid[s]) cp_async16(sdst[s] + nb*sstep[s],
                                         gsrc[s] + (size_t)(c+1)*gstep[s]);
        }
        cp_commit();
        cp_wait1();
        __syncthreads();

        const float* xr = xbase + b*X1BUF;
        const float* wr = wbase + b*X2BUF;
        float4 a0 = *(const float4*)(xr);
        float4 a1 = *(const float4*)(xr + 4);
        float4 q0 = *(const float4*)(wr);
        float4 q1 = *(const float4*)(wr + 4);
        float4 q2 = *(const float4*)(wr + 8);
        float4 q3 = *(const float4*)(wr + 12);

        float xv[8]  = {a0.x,a0.y,a0.z,a0.w, a1.x,a1.y,a1.z,a1.w};
        float win[16] = {q0.x,q0.y,q0.z,q0.w, q1.x,q1.y,q1.z,q1.w,
                         q2.x,q2.y,q2.z,q2.w, q3.x,q3.y,q3.z,q3.w};

        #pragma unroll
        for (int k = 0; k < 9; k++)
            #pragma unroll
            for (int r = 0; r < 8; r++)
                acc[k][r] = fmaf(xv[r], win[r + k], acc[k][r]);

        __syncthreads();
    }

    // ---- Epilogue: mean over C, write 9 k-planes, 2x STG.128 each ----
    const int h = h0 + lh, w = w0 + lw, d0 = seg * 8;
    size_t base = (size_t)(oi*81 + oj*9) * X1_CH + ((size_t)h*HH + w)*HH + d0;
    const float sc = 1.0f / 32.0f;
    #pragma unroll
    for (int k = 0; k < 9; k++) {
        float4 v0 = make_float4(acc[k][0]*sc, acc[k][1]*sc, acc[k][2]*sc, acc[k][3]*sc);
        float4 v1 = make_float4(acc[k][4]*sc, acc[k][5]*sc, acc[k][6]*sc, acc[k][7]*sc);
        float* p = out + base + (size_t)k * X1_CH;
        *(float4*)(p)     = v0;
        *(float4*)(p + 4) = v1;
    }
}

extern "C" void kernel_launch(void* const* d_in, const int* in_sizes, int n_in,
                              void* d_out, int out_size) {
    const float* x1 = (const float*)d_in[0];
    const float* x2 = (const float*)d_in[1];
    float* out = (float*)d_out;

    // Build zero-padded x2 (22.5 MB __device__ scratch). 5,619,712 = 21952 * 256.
    pad_kernel<<<21952, 256>>>(x2);

    cudaFuncSetAttribute(corr_kernel, cudaFuncAttributeMaxDynamicSharedMemorySize,
                         SMEM_FLOATS * 4);
    dim3 grid(6, 6, 81);
    corr_kernel<<<grid, NTHREADS, SMEM_FLOATS * 4>>>(x1, out);
}

// round 5
// speedup vs baseline: 1.3538x; 1.3538x over previous
#include <cuda_runtime.h>
#include <cstdint>

#define HH 48
#define CCH 32
#define PP 56
#define PAD 4
#define X2P_CH (PP*PP*PP)          /* 175616 */
#define X1_CH  (HH*HH*HH)          /* 110592 */

#define TH 4                       /* h-tile */
#define TW 8                       /* w-tile */
#define NSEG 12                    /* 48 / 4 d-voxels per thread */
#define DPT 4
#define NTHREADS 384               /* TH*TW*NSEG */
#define S2 60                      /* x2 smem row stride (floats) */
#define ROWS (TH*TW)               /* 32 x2 rows per CTA */
#define X2BUF (ROWS*S2)            /* 1920 floats per channel buffer */
#define NLD 448                    /* float4 loads per channel: 32 rows * 14 */

// Zero-padded x2: [C][56][56][56]
__device__ float g_x2p[CCH * X2P_CH];

__global__ void pad_kernel(const float* __restrict__ x2) {
    int idx = blockIdx.x * blockDim.x + threadIdx.x;   // exactly 32*175616 threads
    int c   = idx / X2P_CH;
    int rem = idx % X2P_CH;
    int hp  = rem / (PP*PP);
    int wp  = (rem / PP) % PP;
    int dp  = rem % PP;
    int h = hp - PAD, w = wp - PAD, d = dp - PAD;
    float v = 0.f;
    if ((unsigned)h < HH && (unsigned)w < HH && (unsigned)d < HH)
        v = x2[((c*HH + h)*HH + w)*HH + d];
    g_x2p[idx] = v;
}

__device__ __forceinline__ void cp_async16(uint32_t s, const void* g) {
    asm volatile("cp.async.cg.shared.global [%0], [%1], 16;" :: "r"(s), "l"(g));
}
__device__ __forceinline__ void cp_commit() { asm volatile("cp.async.commit_group;"); }
__device__ __forceinline__ void cp_wait0()  { asm volatile("cp.async.wait_group 0;"); }

// Grid: (6 w-tiles, 12 h-tiles, 81 (i,j)). Block: 384 threads, 2 CTAs/SM.
// tid = (lh*8 + lw)*12 + seg ; thread owns (h0+lh, w0+lw, seg*4 .. seg*4+3)
// for all 9 k-offsets of the CTA's fixed (oi,oj).
__global__ void __launch_bounds__(NTHREADS, 2)
corr_kernel(const float* __restrict__ x1, float* __restrict__ out)
{
    __shared__ float smem[2 * X2BUF];

    const int tid = threadIdx.x;
    const int seg = tid % NSEG;          // fastest -> coalesced LDG/STG on d
    const int row = tid / NSEG;          // 0..31 = lh*8 + lw
    const int lw  = row & 7;
    const int lh  = row >> 3;
    const int w0  = blockIdx.x * TW;
    const int h0  = blockIdx.y * TH;
    const int ij  = blockIdx.z;
    const int oi  = ij / 9;
    const int oj  = ij % 9;

    uint32_t smem_u32 = (uint32_t)__cvta_generic_to_shared(smem);

    // ---- cooperative x2-slab load slots: 448 float4 over 384 threads (2 slots) ----
    const char* gsrc[2];
    uint32_t    sdst[2];
    bool        valid[2];
    #pragma unroll
    for (int s = 0; s < 2; s++) {
        int t = tid + s * NTHREADS;
        valid[s] = (t < NLD);
        int r = (t < NLD) ? (t / 14) : 0;
        int col = (t < NLD) ? (t % 14) : 0;
        int hp = h0 + oi + (r >> 3);
        int wp = w0 + oj + (r & 7);
        gsrc[s] = (const char*)(g_x2p + ((size_t)hp * PP + wp) * PP + col * 4);
        sdst[s] = smem_u32 + (uint32_t)(r * S2 + col * 4) * 4;
    }

    float acc[9][DPT];
    #pragma unroll
    for (int k = 0; k < 9; k++)
        #pragma unroll
        for (int r = 0; r < DPT; r++) acc[k][r] = 0.f;

    // x1: private per-thread, register prefetch, no smem
    const float* x1p = x1 + ((size_t)(h0 + lh) * HH + (w0 + lw)) * HH + seg * DPT;
    float4 xnext = *(const float4*)(x1p);

    // Prologue: channel 0 -> buffer 0
    if (valid[0]) cp_async16(sdst[0], gsrc[0]);
    if (valid[1]) cp_async16(sdst[1], gsrc[1]);
    cp_commit();

    const int woff = row * S2 + seg * DPT;

    #pragma unroll 1
    for (int c = 0; c < CCH; c++) {
        const int b = c & 1;
        cp_wait0();          // channel c landed in buffer b
        __syncthreads();     // everyone done reading buffer 1-b (stage c-1 compute)

        if (c + 1 < CCH) {   // overlap: fill the other buffer while computing
            const int nb = 1 - b;
            if (valid[0]) cp_async16(sdst[0] + (uint32_t)nb * X2BUF * 4,
                                     gsrc[0] + (size_t)(c + 1) * X2P_CH * 4);
            if (valid[1]) cp_async16(sdst[1] + (uint32_t)nb * X2BUF * 4,
                                     gsrc[1] + (size_t)(c + 1) * X2P_CH * 4);
            cp_commit();
        }

        float4 xcur = xnext;
        if (c + 1 < CCH) xnext = *(const float4*)(x1p + (size_t)(c + 1) * X1_CH);

        const float* wr = smem + b * X2BUF + woff;
        float4 q0 = *(const float4*)(wr);
        float4 q1 = *(const float4*)(wr + 4);
        float4 q2 = *(const float4*)(wr + 8);
        float win[12] = {q0.x,q0.y,q0.z,q0.w, q1.x,q1.y,q1.z,q1.w,
                         q2.x,q2.y,q2.z,q2.w};
        float xv[4] = {xcur.x, xcur.y, xcur.z, xcur.w};

        #pragma unroll
        for (int k = 0; k < 9; k++)
            #pragma unroll
            for (int r = 0; r < DPT; r++)
                acc[k][r] = fmaf(xv[r], win[r + k], acc[k][r]);
    }

    // ---- Epilogue: mean over C, 9 coalesced STG.128 ----
    const float sc = 1.0f / 32.0f;
    size_t base = (size_t)(oi * 81 + oj * 9) * X1_CH
                + ((size_t)(h0 + lh) * HH + (w0 + lw)) * HH + seg * DPT;
    #pragma unroll
    for (int k = 0; k < 9; k++) {
        float4 v = make_float4(acc[k][0]*sc, acc[k][1]*sc, acc[k][2]*sc, acc[k][3]*sc);
        *(float4*)(out + base + (size_t)k * X1_CH) = v;
    }
}

extern "C" void kernel_launch(void* const* d_in, const int* in_sizes, int n_in,
                              void* d_out, int out_size) {
    const float* x1 = (const float*)d_in[0];
    const float* x2 = (const float*)d_in[1];
    float* out = (float*)d_out;

    pad_kernel<<<21952, 256>>>(x2);   // 32*175616 = 21952*256 threads

    dim3 grid(6, 12, 81);
    corr_kernel<<<grid, NTHREADS>>>(x1, out);
}